// round 17
// baseline (speedup 1.0000x reference)
#include <cuda_runtime.h>

#define NB 8
#define NV 100000
#define NF 200000
#define BN (NB * NV)
#define TOTF (NB * NF)
#define PAIRS (TOTF / 2)
#define HALF (BN / 2)

// scratch: per-vertex accumulator (dx, dy, dz, unused) — 12.8 MB, L2-resident.
// Differential form: accumulates w * (V[other] - V[self]) so finalize needs
// no V read: out[v] = acc[v].xyz.
__device__ float4 g_acc[BN];
// padded, 16B-aligned copy of V for single-LDG.128 gathers
__device__ float4 g_V4[BN];
__device__ int g_is32;   // 1 if F is int32, 0 if int64

// Prep: dtype detect + zero accumulators + pad V into float4.
// TWO vertices per thread from disjoint halves -> 6 independent DRAM loads
// in flight per thread (2x MLP vs one-vertex version) at full thread count.
__global__ void __launch_bounds__(256) prep_k(const float* __restrict__ V,
                                              const long long* __restrict__ F64,
                                              int nwords) {
    int t = blockIdx.x * blockDim.x + threadIdx.x;

    if (blockIdx.x == 0 && threadIdx.x < 32) {
        int lane = threadIdx.x;
        int bad = 0;
        int n = nwords < 1024 ? nwords : 1024;
        #pragma unroll
        for (int k = 0; k < 32; k++) {
            int i = lane + k * 32;
            if (i < n) {
                long long x = F64[i];
                bad |= (x < 0 || x >= NV) ? 1 : 0;
            }
        }
        unsigned m = __ballot_sync(0xFFFFFFFFu, bad);
        if (lane == 0) g_is32 = (m != 0) ? 1 : 0;
    }

    if (t >= HALF) return;
    int va = t;
    int vb = t + HALF;
    const float* pa = V + (size_t)va * 3;
    const float* pb = V + (size_t)vb * 3;
    // issue all 6 loads before any store (compiler batches: independent)
    float ax = pa[0], ay = pa[1], az = pa[2];
    float bx = pb[0], by = pb[1], bz = pb[2];
    float4 z = make_float4(0.f, 0.f, 0.f, 0.f);
    g_V4[va] = make_float4(ax, ay, az, 0.f);
    g_V4[vb] = make_float4(bx, by, bz, 0.f);
    g_acc[va] = z;
    g_acc[vb] = z;
}

__device__ __forceinline__ int clampi(int v, int lo, int hi) {
    return v < lo ? lo : (v > hi ? hi : v);
}

__device__ __forceinline__ void red_v4(float4* addr, float x, float y, float z, float w) {
    asm volatile("red.global.add.v4.f32 [%0], {%1, %2, %3, %4};"
                 :: "l"(addr), "f"(x), "f"(y), "f"(z), "f"(w)
                 : "memory");
}

// Core per-face computation (differential form).
__device__ __forceinline__ void face_body(int i0, int i1, int i2,
                                          float4 P0, float4 P1, float4 P2) {
    float x0 = P0.x, y0 = P0.y, z0 = P0.z;
    float x1 = P1.x, y1 = P1.y, z1 = P1.z;
    float x2 = P2.x, y2 = P2.y, z2 = P2.z;

    float ax = x1 - x2, ay = y1 - y2, az = z1 - z2;  // v1 - v2
    float bx = x2 - x0, by = y2 - y0, bz = z2 - z0;  // v2 - v0
    float cx = x0 - x1, cy = y0 - y1, cz = z0 - z1;  // v0 - v1
    float d1 = ax * ax + ay * ay + az * az;
    float d2 = bx * bx + by * by + bz * bz;
    float d3 = cx * cx + cy * cy + cz * cz;
    float l1 = sqrtf(d1), l2 = sqrtf(d2), l3 = sqrtf(d3);
    float sp = 0.5f * (l1 + l2 + l3);
    float inside = sp * (sp - l1) * (sp - l2) * (sp - l3);
    inside = fmaxf(inside, 0.0f);
    float A = 2.0f * sqrtf(inside);
    float inv = 0.25f / (A + 1e-10f);
    if (A == 0.0f) inv = 0.0f;

    float w23 = (d2 + d3 - d1) * inv;  // edge (v1,v2)
    float w31 = (d1 + d3 - d2) * inv;  // edge (v2,v0)
    float w12 = (d1 + d2 - d3) * inv;  // edge (v0,v1)

    red_v4(&g_acc[i0], w31 * bx - w12 * cx, w31 * by - w12 * cy,
                       w31 * bz - w12 * cz, 0.f);
    red_v4(&g_acc[i1], w12 * cx - w23 * ax, w12 * cy - w23 * ay,
                       w12 * cz - w23 * az, 0.f);
    red_v4(&g_acc[i2], w23 * ax - w31 * bx, w23 * ay - w31 * by,
                       w23 * az - w31 * bz, 0.f);
}

// Two faces per thread; 2-D grid: blockIdx.y = batch (no integer division).
__global__ void __launch_bounds__(256) face_k(const void* __restrict__ Fraw) {
    int p = blockIdx.x * blockDim.x + threadIdx.x;      // pair index in batch
    if (p >= NF / 2) return;
    int batch = blockIdx.y;
    int base = batch * NV;
    size_t gp = (size_t)batch * (NF / 2) + p;           // global pair index

    int fa0, fa1, fa2, fb0, fb1, fb2;
    if (g_is32) {
        const int2* fp = (const int2*)Fraw + gp * 3;
        int2 q0 = __ldg(&fp[0]);
        int2 q1 = __ldg(&fp[1]);
        int2 q2 = __ldg(&fp[2]);
        fa0 = q0.x; fa1 = q0.y; fa2 = q1.x;
        fb0 = q1.y; fb1 = q2.x; fb2 = q2.y;
    } else {
        const longlong2* fp = (const longlong2*)Fraw + gp * 3;
        longlong2 q0 = __ldg(&fp[0]);
        longlong2 q1 = __ldg(&fp[1]);
        longlong2 q2 = __ldg(&fp[2]);
        fa0 = (int)q0.x; fa1 = (int)q0.y; fa2 = (int)q1.x;
        fb0 = (int)q1.y; fb1 = (int)q2.x; fb2 = (int)q2.y;
    }
    fa0 = clampi(fa0, 0, NV - 1); fa1 = clampi(fa1, 0, NV - 1); fa2 = clampi(fa2, 0, NV - 1);
    fb0 = clampi(fb0, 0, NV - 1); fb1 = clampi(fb1, 0, NV - 1); fb2 = clampi(fb2, 0, NV - 1);

    int ia0 = base + fa0, ia1 = base + fa1, ia2 = base + fa2;
    int ib0 = base + fb0, ib1 = base + fb1, ib2 = base + fb2;

    float4 A0 = __ldg(&g_V4[ia0]);
    float4 A1 = __ldg(&g_V4[ia1]);
    float4 A2 = __ldg(&g_V4[ia2]);
    float4 B0 = __ldg(&g_V4[ib0]);
    float4 B1 = __ldg(&g_V4[ib1]);
    float4 B2 = __ldg(&g_V4[ib2]);

    face_body(ia0, ia1, ia2, A0, A1, A2);
    face_body(ib0, ib1, ib2, B0, B1, B2);
}

// out[v] = acc[v].xyz — no V read needed (differential accumulation).
__global__ void __launch_bounds__(256) fin_k(float* __restrict__ out) {
    int v = blockIdx.x * blockDim.x + threadIdx.x;
    if (v < BN) {
        float4 a = g_acc[v];
        float* o = out + (size_t)v * 3;
        o[0] = a.x;
        o[1] = a.y;
        o[2] = a.z;
    }
}

extern "C" void kernel_launch(void* const* d_in, const int* in_sizes, int n_in,
                              void* d_out, int out_size) {
    // Robust slot selection: V has BN*3 = 2.4M elements, F has TOTF*3 = 4.8M.
    const float* V;
    const void* F;
    int f_elems;
    if (in_sizes[0] == BN * 3) {
        V = (const float*)d_in[0];
        F = d_in[1];
        f_elems = in_sizes[1];
    } else {
        V = (const float*)d_in[1];
        F = d_in[0];
        f_elems = in_sizes[0];
    }
    float* out = (float*)d_out;

    prep_k<<<(HALF + 255) / 256, 256>>>(V, (const long long*)F, f_elems / 2);
    dim3 fgrid((NF / 2 + 255) / 256, NB);
    face_k<<<fgrid, 256>>>(F);
    fin_k<<<(BN + 255) / 256, 256>>>(out);
}